// round 2
// baseline (speedup 1.0000x reference)
#include <cuda_runtime.h>
#include <math.h>

#define NB 64          // batch
#define SEQ 64         // seq len
#define MD 256         // model dim
#define HF 128         // half
#define NG 640         // 5 * HF gates
#define WD 300         // word dim
#define MLPD 1024
#define NC 3

// Scratch (device globals — no runtime allocation allowed)
__device__ float g_states[2][NB * SEQ * MD];   // ping-pong state buffers (4 MB each)
__device__ float g_gates[NB * (SEQ - 1) * NG]; // gate pre-activations (10.3 MB)
__device__ float g_comp[NB * (SEQ - 1) * MD];  // TreeLSTM outputs (4.1 MB)

__device__ __forceinline__ float sigf(float x) { return 1.0f / (1.0f + expf(-x)); }

// ---------------------------------------------------------------------------
// Encoder: states0[b][t][:] = embed[sent[b][t]] @ W_enc + b_enc
// 16 tokens per block, 256 threads (one output column each)
// ---------------------------------------------------------------------------
__global__ void encode_kernel(const int* __restrict__ sent,
                              const float* __restrict__ emb,
                              const float* __restrict__ W,
                              const float* __restrict__ bias) {
    __shared__ float se[16][WD];
    const int tok0 = blockIdx.x * 16;
    const int tid = threadIdx.x;
    for (int i = tid; i < 16 * WD; i += 256) {
        int t = i / WD, k = i - t * WD;
        se[t][k] = emb[(size_t)sent[tok0 + t] * WD + k];
    }
    __syncthreads();
    const int n = tid;
    float acc[16];
    float bv = bias[n];
#pragma unroll
    for (int t = 0; t < 16; t++) acc[t] = bv;
    for (int k = 0; k < WD; k++) {
        float w = W[k * MD + n];
#pragma unroll
        for (int t = 0; t < 16; t++) acc[t] += se[t][k] * w;
    }
    float* out = g_states[0];
#pragma unroll
    for (int t = 0; t < 16; t++) out[(size_t)(tok0 + t) * MD + n] = acc[t];
}

// ---------------------------------------------------------------------------
// Gates GEMM: gates[r][n] = concat(h_l, h_r)[r] @ W_comp[:, n] + b_comp[n]
// Row r = b*P + p maps to x[k] = S[b][p][k] (k<128) / S[b][p+1][k-128] (k>=128)
//       = S + rowbase + k + (k>=128 ? 128 : 0)
// Register-tiled fp32 GEMM. M = 64*P is always a multiple of BM=64 -> no guards.
// ---------------------------------------------------------------------------
template <int BM, int BN, int TM, int TN>
__global__ void gates_gemm(const float* __restrict__ W,
                           const float* __restrict__ bias,
                           int P, int in) {
    constexpr int BK = 16;
    constexpr int TX = BN / TN;          // 16
    constexpr int TY = BM / TM;          // 16
    constexpr int THREADS = TX * TY;     // 256
    __shared__ __align__(16) float Xs[BK][BM];
    __shared__ __align__(16) float Ws[BK][BN];
    __shared__ int rowoff[BM];

    const float* __restrict__ S = g_states[in];
    const int tid = threadIdx.x;
    const int m0 = blockIdx.x * BM;
    const int n0 = blockIdx.y * BN;

    for (int m = tid; m < BM; m += THREADS) {
        int r = m0 + m;
        int b = r / P;
        int p = r - b * P;
        rowoff[m] = b * (SEQ * MD) + p * MD;
    }

    const int tx = tid % TX;
    const int ty = tid / TX;

    float acc[TM][TN];
#pragma unroll
    for (int i = 0; i < TM; i++)
#pragma unroll
        for (int j = 0; j < TN; j++) acc[i][j] = 0.f;

    __syncthreads();

    for (int kt = 0; kt < MD; kt += BK) {
        // X tile: BM*BK floats, float4 per thread (transposed into [k][m])
        for (int i = tid; i < BM * BK / 4; i += THREADS) {
            int m = i / (BK / 4);
            int kq = i - m * (BK / 4);
            int kg = kt + kq * 4;
            int addr = rowoff[m] + kg + ((kg >= HF) ? HF : 0);
            float4 v = *reinterpret_cast<const float4*>(S + addr);
            Xs[kq * 4 + 0][m] = v.x;
            Xs[kq * 4 + 1][m] = v.y;
            Xs[kq * 4 + 2][m] = v.z;
            Xs[kq * 4 + 3][m] = v.w;
        }
        // W tile: BK*BN floats
        for (int i = tid; i < BK * BN / 4; i += THREADS) {
            int k = i / (BN / 4);
            int n4 = i - k * (BN / 4);
            *reinterpret_cast<float4*>(&Ws[k][n4 * 4]) =
                *reinterpret_cast<const float4*>(W + (size_t)(kt + k) * NG + n0 + n4 * 4);
        }
        __syncthreads();
#pragma unroll
        for (int k = 0; k < BK; k++) {
            float a[TM], bb[TN];
#pragma unroll
            for (int i = 0; i < TM / 4; i++) {
                float4 v = *reinterpret_cast<const float4*>(&Xs[k][ty * TM + 4 * i]);
                a[4 * i + 0] = v.x; a[4 * i + 1] = v.y;
                a[4 * i + 2] = v.z; a[4 * i + 3] = v.w;
            }
#pragma unroll
            for (int j = 0; j < TN / 4; j++) {
                float4 v = *reinterpret_cast<const float4*>(&Ws[k][tx * TN + 4 * j]);
                bb[4 * j + 0] = v.x; bb[4 * j + 1] = v.y;
                bb[4 * j + 2] = v.z; bb[4 * j + 3] = v.w;
            }
#pragma unroll
            for (int i = 0; i < TM; i++)
#pragma unroll
                for (int j = 0; j < TN; j++) acc[i][j] += a[i] * bb[j];
        }
        __syncthreads();
    }

#pragma unroll
    for (int i = 0; i < TM; i++) {
        int r = m0 + ty * TM + i;
        float* g = g_gates + (size_t)r * NG + n0 + tx * TN;
#pragma unroll
        for (int j = 0; j < TN; j++) g[j] = acc[i][j] + bias[n0 + tx * TN + j];
    }
}

// ---------------------------------------------------------------------------
// Per-layer combine: TreeLSTM activations, selection logits, stable softmax,
// cumsum, soft reduction. One block per batch row (all positions in-block).
// ---------------------------------------------------------------------------
__global__ void combine_kernel(const float* __restrict__ Wsel,
                               const float* __restrict__ bsel,
                               int P, int in) {
    const int b = blockIdx.x;
    const int tid = threadIdx.x;
    __shared__ float wsel_s[MD];
    __shared__ float lg[64], es[64], cs[64];
    __shared__ float prw[64], clw[64], crw[64];
    __shared__ float smax, sinv, stot;

    const float* __restrict__ Sin = g_states[in] + (size_t)b * SEQ * MD;
    float* __restrict__ Sout = g_states[in ^ 1] + (size_t)b * SEQ * MD;
    const float* __restrict__ Gb = g_gates + (size_t)b * P * NG;
    float* __restrict__ Cb = g_comp + (size_t)b * (SEQ - 1) * MD;

    for (int i = tid; i < MD; i += 256) wsel_s[i] = Wsel[i];
    __syncthreads();

    // Phase 1: TreeLSTM cell -> comp = [h, c]
    for (int idx = tid; idx < P * HF; idx += 256) {
        int p = idx / HF, j = idx - p * HF;
        const float* g = Gb + (size_t)p * NG;
        float av = g[j];
        float iv = g[HF + j];
        float f1 = g[2 * HF + j];
        float f2 = g[3 * HF + j];
        float ov = g[4 * HF + j];
        float c_l = Sin[p * MD + HF + j];
        float c_r = Sin[(p + 1) * MD + HF + j];
        float c = tanhf(av) * sigf(iv) + sigf(f1) * c_l + sigf(f2) * c_r;
        float h = sigf(ov) * tanhf(c);
        Cb[p * MD + j] = h;
        Cb[p * MD + HF + j] = c;
    }
    __syncthreads();

    // Phase 2: logits[p] = comp[p] . W_sel + b_sel  (4 threads per position)
    {
        int p = tid >> 2, q = tid & 3;
        int pc = (p < P) ? p : (P - 1);
        const float* cp = Cb + (size_t)pc * MD;
        float s = 0.f;
        int k0 = q * 64;
#pragma unroll 8
        for (int k = 0; k < 64; k++) s += cp[k0 + k] * wsel_s[k0 + k];
        s += __shfl_down_sync(0xFFFFFFFFu, s, 2);
        s += __shfl_down_sync(0xFFFFFFFFu, s, 1);
        if (q == 0 && p < P) lg[p] = s + bsel[0];
    }
    __syncthreads();

    // Phase 3: stable softmax + inclusive scan (Hillis-Steele over 64 slots)
    if (tid < 32) {
        float v = (tid < P) ? lg[tid] : -1e30f;
        float v2 = (tid + 32 < P) ? lg[tid + 32] : -1e30f;
        v = fmaxf(v, v2);
        for (int o = 16; o > 0; o >>= 1) v = fmaxf(v, __shfl_xor_sync(0xFFFFFFFFu, v, o));
        if (tid == 0) smax = v;
    }
    __syncthreads();
    if (tid < 64) {
        float e = (tid < P) ? expf(lg[tid] - smax) : 0.f;
        es[tid] = e;
        cs[tid] = e;
    }
    __syncthreads();
    for (int off = 1; off < 64; off <<= 1) {
        float v = 0.f;
        if (tid < 64) { v = cs[tid]; if (tid >= off) v += cs[tid - off]; }
        __syncthreads();
        if (tid < 64) cs[tid] = v;
        __syncthreads();
    }
    if (tid == 0) { stot = cs[P - 1]; sinv = 1.f / stot; }
    __syncthreads();
    if (tid < 64) {
        float inv = sinv;
        float e = es[tid];
        float csv = cs[tid];
        prw[tid] = e * inv;                 // probs[p]
        crw[tid] = (csv - e) * inv;         // copy_right = exclusive cumsum
        clw[tid] = (stot - csv) * inv;      // copy_left  = total - inclusive
    }
    __syncthreads();

    // Phase 4: new_states[p] = cl*left + cr*right + pr*comp   (d = tid)
    {
        const int d = tid;
        for (int p = 0; p < P; p++) {
            float lv = Sin[p * MD + d];
            float rv = Sin[(p + 1) * MD + d];
            float cv = Cb[p * MD + d];
            Sout[p * MD + d] = clw[p] * lv + crw[p] * rv + prw[p] * cv;
        }
    }
}

// ---------------------------------------------------------------------------
// Final MLP: relu(relu(h@W1+b1)@W2+b2)@W_out + b_out. One block per row.
// ---------------------------------------------------------------------------
__global__ void mlp_kernel(const float* __restrict__ W1, const float* __restrict__ b1,
                           const float* __restrict__ W2, const float* __restrict__ b2,
                           const float* __restrict__ Wo, const float* __restrict__ bo,
                           float* __restrict__ out, int in) {
    const int b = blockIdx.x, tid = threadIdx.x;
    __shared__ float h0[MD];
    __shared__ float h1[MLPD];
    __shared__ float h2[MLPD];
    __shared__ float red[256];
    const float* S = g_states[in] + (size_t)b * SEQ * MD;
    for (int i = tid; i < MD; i += 256) h0[i] = S[i];
    __syncthreads();
#pragma unroll
    for (int ni = 0; ni < MLPD / 256; ni++) {
        int n = tid + ni * 256;
        float acc = b1[n];
        for (int k = 0; k < MD; k++) acc += h0[k] * W1[(size_t)k * MLPD + n];
        h1[n] = fmaxf(acc, 0.f);
    }
    __syncthreads();
#pragma unroll
    for (int ni = 0; ni < MLPD / 256; ni++) {
        int n = tid + ni * 256;
        float acc = b2[n];
        for (int k = 0; k < MLPD; k++) acc += h1[k] * W2[(size_t)k * MLPD + n];
        h2[n] = fmaxf(acc, 0.f);
    }
    __syncthreads();
    for (int c = 0; c < NC; c++) {
        float part = 0.f;
        for (int k = tid; k < MLPD; k += 256) part += h2[k] * Wo[(size_t)k * NC + c];
        red[tid] = part;
        __syncthreads();
        for (int s = 128; s > 0; s >>= 1) {
            if (tid < s) red[tid] += red[tid + s];
            __syncthreads();
        }
        if (tid == 0) out[b * NC + c] = red[0] + bo[c];
        __syncthreads();
    }
}

// ---------------------------------------------------------------------------
extern "C" void kernel_launch(void* const* d_in, const int* in_sizes, int n_in,
                              void* d_out, int out_size) {
    const int*   sent   = (const int*)  d_in[0];
    const float* emb    = (const float*)d_in[1];
    const float* W_enc  = (const float*)d_in[2];
    const float* b_enc  = (const float*)d_in[3];
    const float* W_comp = (const float*)d_in[4];
    const float* b_comp = (const float*)d_in[5];
    const float* W_sel  = (const float*)d_in[6];
    const float* b_sel  = (const float*)d_in[7];
    const float* W1     = (const float*)d_in[8];
    const float* b1     = (const float*)d_in[9];
    const float* W2     = (const float*)d_in[10];
    const float* b2     = (const float*)d_in[11];
    const float* Wo     = (const float*)d_in[12];
    const float* bo     = (const float*)d_in[13];
    float* out = (float*)d_out;

    encode_kernel<<<NB * SEQ / 16, 256>>>(sent, emb, W_enc, b_enc);

    int cur = 0;
    for (int P = SEQ - 1; P >= 1; --P) {
        if (P >= 18) {
            dim3 grid(P, NG / 128);  // M tiles = 64P/64 = P exactly
            gates_gemm<64, 128, 4, 8><<<grid, 256>>>(W_comp, b_comp, P, cur);
        } else {
            dim3 grid(P, NG / 64);
            gates_gemm<64, 64, 4, 4><<<grid, 256>>>(W_comp, b_comp, P, cur);
        }
        combine_kernel<<<NB, 256>>>(W_sel, b_sel, P, cur);
        cur ^= 1;
    }

    mlp_kernel<<<NB, 256>>>(W1, b1, W2, b2, Wo, bo, out, cur);
}

// round 5
// speedup vs baseline: 1.2933x; 1.2933x over previous
#include <cuda_runtime.h>
#include <math.h>

#define NB 64          // batch
#define SEQ 64         // seq len
#define MD 256         // model dim
#define HF 128         // half
#define WD 300         // word dim
#define MLPD 1024
#define NC 3
#define BK 16          // K tile
#define XSTR 36        // Xs row stride (BM=32 + pad, 16B-aligned)

// Scratch (device globals — no runtime allocation allowed)
__device__ float g_states[2][NB * SEQ * MD];     // ping-pong state buffers
__device__ float g_comp[NB * (SEQ - 1) * MD];    // TreeLSTM [h,c] outputs
__device__ float g_lgpart[NB * (SEQ - 1) * 2];   // selection-logit partials (2 j-chunks)

__device__ __forceinline__ float sig_f(float x) { return 1.0f / (1.0f + __expf(-x)); }
__device__ __forceinline__ float tanh_f(float x) { return 1.0f - 2.0f / (__expf(2.0f * x) + 1.0f); }

// Packed f32x2 helpers (sm_100a; ptxas never auto-fuses these)
__device__ __forceinline__ unsigned long long pack2(float lo, float hi) {
    unsigned long long p;
    asm("mov.b64 %0, {%1, %2};" : "=l"(p) : "f"(lo), "f"(hi));
    return p;
}
__device__ __forceinline__ void unpack2(unsigned long long p, float& lo, float& hi) {
    asm("mov.b64 {%0, %1}, %2;" : "=f"(lo), "=f"(hi) : "l"(p));
}
__device__ __forceinline__ void fma2(unsigned long long& d, unsigned long long a, unsigned long long b) {
    asm("fma.rn.f32x2 %0, %1, %2, %0;" : "+l"(d) : "l"(a), "l"(b));
}

// ---------------------------------------------------------------------------
// Encoder: states0[b][t][:] = embed[sent[b][t]] @ W_enc + b_enc
// ---------------------------------------------------------------------------
__global__ void encode_kernel(const int* __restrict__ sent,
                              const float* __restrict__ emb,
                              const float* __restrict__ W,
                              const float* __restrict__ bias) {
    __shared__ float se[16][WD];
    const int tok0 = blockIdx.x * 16;
    const int tid = threadIdx.x;
    for (int i = tid; i < 16 * WD; i += 256) {
        int t = i / WD, k = i - t * WD;
        se[t][k] = emb[(size_t)sent[tok0 + t] * WD + k];
    }
    __syncthreads();
    const int n = tid;
    float acc[16];
    float bv = bias[n];
#pragma unroll
    for (int t = 0; t < 16; t++) acc[t] = bv;
    for (int k = 0; k < WD; k++) {
        float w = W[k * MD + n];
#pragma unroll
        for (int t = 0; t < 16; t++) acc[t] += se[t][k] * w;
    }
    float* out = g_states[0];
#pragma unroll
    for (int t = 0; t < 16; t++) out[(size_t)(tok0 + t) * MD + n] = acc[t];
}

// ---------------------------------------------------------------------------
// Fused GEMM + TreeLSTM cell + logit partial.
// Tile: BM = TM*8 rows x 64 gate-columns (j-chunk jc = blockIdx.y), all 5 gates.
// Lane tx owns gate columns {j0+2tx, j0+2tx+1} -> W operand is a pre-packed
// f32x2 loaded with a single LDS.64. Warp ty owns rows ty*TM..ty*TM+TM-1;
// A-operand LDS.128 is warp-uniform (broadcast). Inner loop: 5*TM FFMA2.
// ---------------------------------------------------------------------------
template <int TM>
__global__ __launch_bounds__(256)
void gates_gemm(const float* __restrict__ Wc, const float* __restrict__ bc,
                const float* __restrict__ Wsel, int P, int in) {
    constexpr int BM = TM * 8;
    __shared__ float Xs[BK * XSTR];
    __shared__ float Ws[BK * 320];           // [k][g*64 + j], j in [0,64)
    __shared__ int rowoff_s[BM];

    const float* __restrict__ S = g_states[in];
    const int tid = threadIdx.x;
    const int tx = tid & 31, ty = tid >> 5;
    const int jc = blockIdx.y;               // 0 or 1
    const int j0 = jc * 64;
    const int m0 = blockIdx.x * BM;

    for (int m = tid; m < BM; m += 256) {
        int r = m0 + m;
        int b = r / P;
        int p = r - b * P;
        rowoff_s[m] = b * (SEQ * MD) + p * MD;
    }

    unsigned long long acc[TM][5];
#pragma unroll
    for (int i = 0; i < TM; i++)
#pragma unroll
        for (int g = 0; g < 5; g++) acc[i][g] = 0ull;

    __syncthreads();

    for (int kt = 0; kt < MD; kt += BK) {
        const int xoff = kt + ((kt >= HF) ? HF : 0);
        // X tile: BM*BK floats -> Xs[k][m] (transposed, stride XSTR)
        for (int s = tid; s < BM * (BK / 4); s += 256) {
            int m = s >> 2;                  // BK/4 = 4
            int kq = s & 3;
            float4 v = *reinterpret_cast<const float4*>(S + rowoff_s[m] + xoff + kq * 4);
            float* xp = Xs + (kq * 4) * XSTR + m;
            xp[0 * XSTR] = v.x; xp[1 * XSTR] = v.y;
            xp[2 * XSTR] = v.z; xp[3 * XSTR] = v.w;
        }
        // W tile: BK*320 floats = 1280 float4 (5 per thread)
        for (int s = tid; s < BK * 80; s += 256) {
            int k = s / 80;
            int rem = s - k * 80;
            int g = rem >> 4, j4 = rem & 15;
            *reinterpret_cast<float4*>(Ws + k * 320 + g * 64 + j4 * 4) =
                *reinterpret_cast<const float4*>(Wc + (size_t)(kt + k) * 640 + g * 128 + j0 + j4 * 4);
        }
        __syncthreads();
#pragma unroll
        for (int k = 0; k < BK; k++) {
            const float* wp = Ws + k * 320 + 2 * tx;
            unsigned long long w0 = *reinterpret_cast<const unsigned long long*>(wp);
            unsigned long long w1 = *reinterpret_cast<const unsigned long long*>(wp + 64);
            unsigned long long w2 = *reinterpret_cast<const unsigned long long*>(wp + 128);
            unsigned long long w3 = *reinterpret_cast<const unsigned long long*>(wp + 192);
            unsigned long long w4 = *reinterpret_cast<const unsigned long long*>(wp + 256);
            const float* xp = Xs + k * XSTR + ty * TM;
#pragma unroll
            for (int i = 0; i < TM; i += 4) {
                float4 v = *reinterpret_cast<const float4*>(xp + i);
                unsigned long long a0 = pack2(v.x, v.x);
                unsigned long long a1 = pack2(v.y, v.y);
                unsigned long long a2 = pack2(v.z, v.z);
                unsigned long long a3 = pack2(v.w, v.w);
                fma2(acc[i + 0][0], a0, w0); fma2(acc[i + 0][1], a0, w1);
                fma2(acc[i + 0][2], a0, w2); fma2(acc[i + 0][3], a0, w3);
                fma2(acc[i + 0][4], a0, w4);
                if (TM > 1) {
                    fma2(acc[i + 1][0], a1, w0); fma2(acc[i + 1][1], a1, w1);
                    fma2(acc[i + 1][2], a1, w2); fma2(acc[i + 1][3], a1, w3);
                    fma2(acc[i + 1][4], a1, w4);
                }
                if (TM > 2) {
                    fma2(acc[i + 2][0], a2, w0); fma2(acc[i + 2][1], a2, w1);
                    fma2(acc[i + 2][2], a2, w2); fma2(acc[i + 2][3], a2, w3);
                    fma2(acc[i + 2][4], a2, w4);
                    fma2(acc[i + 3][0], a3, w0); fma2(acc[i + 3][1], a3, w1);
                    fma2(acc[i + 3][2], a3, w2); fma2(acc[i + 3][3], a3, w3);
                    fma2(acc[i + 3][4], a3, w4);
                }
            }
        }
        __syncthreads();
    }

    // Epilogue: bias + TreeLSTM cell + comp write + logit partial (2 cols/lane)
    const int j = j0 + 2 * tx;
    float2 wsh = *reinterpret_cast<const float2*>(Wsel + j);
    float2 wsc = *reinterpret_cast<const float2*>(Wsel + HF + j);
    float2 bb0 = *reinterpret_cast<const float2*>(bc + j);
    float2 bb1 = *reinterpret_cast<const float2*>(bc + 128 + j);
    float2 bb2 = *reinterpret_cast<const float2*>(bc + 256 + j);
    float2 bb3 = *reinterpret_cast<const float2*>(bc + 384 + j);
    float2 bb4 = *reinterpret_cast<const float2*>(bc + 512 + j);
#pragma unroll
    for (int i = 0; i < TM; i++) {
        int m = ty * TM + i;
        int r = m0 + m;
        int roff = rowoff_s[m];
        float2 cl = *reinterpret_cast<const float2*>(S + roff + HF + j);
        float2 cr = *reinterpret_cast<const float2*>(S + roff + MD + HF + j);
        float a0, a1, i0, i1, f10, f11, f20, f21, o0, o1;
        unpack2(acc[i][0], a0, a1);
        unpack2(acc[i][1], i0, i1);
        unpack2(acc[i][2], f10, f11);
        unpack2(acc[i][3], f20, f21);
        unpack2(acc[i][4], o0, o1);
        float c0 = tanh_f(a0 + bb0.x) * sig_f(i0 + bb1.x)
                 + sig_f(f10 + bb2.x) * cl.x + sig_f(f20 + bb3.x) * cr.x;
        float c1 = tanh_f(a1 + bb0.y) * sig_f(i1 + bb1.y)
                 + sig_f(f11 + bb2.y) * cl.y + sig_f(f21 + bb3.y) * cr.y;
        float h0 = sig_f(o0 + bb4.x) * tanh_f(c0);
        float h1 = sig_f(o1 + bb4.y) * tanh_f(c1);
        float* cp = g_comp + (size_t)r * MD;
        *reinterpret_cast<float2*>(cp + j) = make_float2(h0, h1);
        *reinterpret_cast<float2*>(cp + HF + j) = make_float2(c0, c1);
        float part = h0 * wsh.x + h1 * wsh.y + c0 * wsc.x + c1 * wsc.y;
#pragma unroll
        for (int o = 16; o > 0; o >>= 1) part += __shfl_xor_sync(0xFFFFFFFFu, part, o);
        if (tx == 0) g_lgpart[r * 2 + jc] = part;
    }
}

// ---------------------------------------------------------------------------
// Per-layer softmax + soft state update. 4 blocks per batch row (q = sub-slice);
// each block recomputes the 63-wide softmax (cheap) then updates p = q mod 4.
// ---------------------------------------------------------------------------
__global__ __launch_bounds__(256)
void update_kernel(int P, int in) {
    __shared__ float lg[64], es[64], csn[64];
    __shared__ float prw[64], clw[64], crw[64];
    __shared__ float s_max, s_inv, s_tot;
    const int b = blockIdx.x >> 2, q = blockIdx.x & 3;
    const int tid = threadIdx.x;

    if (tid < 64) {
        float l = -3.0e38f;
        if (tid < P) {
            float2 v = *reinterpret_cast<const float2*>(g_lgpart + (((size_t)b * P + tid) << 1));
            l = v.x + v.y;
        }
        lg[tid] = l;
    }
    __syncthreads();
    if (tid < 32) {
        float v = fmaxf(lg[tid], lg[tid + 32]);
        for (int o = 16; o > 0; o >>= 1) v = fmaxf(v, __shfl_xor_sync(0xFFFFFFFFu, v, o));
        if (tid == 0) s_max = v;
    }
    __syncthreads();
    if (tid < 64) {
        float e = (tid < P) ? __expf(lg[tid] - s_max) : 0.f;
        es[tid] = e; csn[tid] = e;
    }
    __syncthreads();
    for (int off = 1; off < 64; off <<= 1) {
        float v = 0.f;
        if (tid < 64) { v = csn[tid]; if (tid >= off) v += csn[tid - off]; }
        __syncthreads();
        if (tid < 64) csn[tid] = v;
        __syncthreads();
    }
    if (tid == 0) { s_tot = csn[P - 1]; s_inv = 1.f / csn[P - 1]; }
    __syncthreads();
    if (tid < 64) {
        float inv = s_inv, e = es[tid], cv = csn[tid];
        prw[tid] = e * inv;
        crw[tid] = (cv - e) * inv;
        clw[tid] = (s_tot - cv) * inv;
    }
    __syncthreads();
    const float* Sb = g_states[in] + b * SEQ * MD;
    float* Ob = g_states[in ^ 1] + b * SEQ * MD;
    const float* Cb = g_comp + (size_t)b * P * MD;
    for (int p = q; p < P; p += 4) {
        Ob[p * MD + tid] = clw[p] * Sb[p * MD + tid]
                         + crw[p] * Sb[(p + 1) * MD + tid]
                         + prw[p] * Cb[p * MD + tid];
    }
}

// ---------------------------------------------------------------------------
// Final MLP: relu(relu(h@W1+b1)@W2+b2)@W_out + b_out. One block per row.
// ---------------------------------------------------------------------------
__global__ void mlp_kernel(const float* __restrict__ W1, const float* __restrict__ b1,
                           const float* __restrict__ W2, const float* __restrict__ b2,
                           const float* __restrict__ Wo, const float* __restrict__ bo,
                           float* __restrict__ out, int in) {
    const int b = blockIdx.x, tid = threadIdx.x;
    __shared__ float h0[MD];
    __shared__ float h1[MLPD];
    __shared__ float h2[MLPD];
    __shared__ float red[256];
    const float* S = g_states[in] + (size_t)b * SEQ * MD;
    for (int i = tid; i < MD; i += 256) h0[i] = S[i];
    __syncthreads();
#pragma unroll
    for (int ni = 0; ni < MLPD / 256; ni++) {
        int n = tid + ni * 256;
        float acc = b1[n];
        for (int k = 0; k < MD; k++) acc += h0[k] * W1[(size_t)k * MLPD + n];
        h1[n] = fmaxf(acc, 0.f);
    }
    __syncthreads();
#pragma unroll
    for (int ni = 0; ni < MLPD / 256; ni++) {
        int n = tid + ni * 256;
        float acc = b2[n];
        for (int k = 0; k < MLPD; k++) acc += h1[k] * W2[(size_t)k * MLPD + n];
        h2[n] = fmaxf(acc, 0.f);
    }
    __syncthreads();
    for (int c = 0; c < NC; c++) {
        float part = 0.f;
        for (int k = tid; k < MLPD; k += 256) part += h2[k] * Wo[(size_t)k * NC + c];
        red[tid] = part;
        __syncthreads();
        for (int s = 128; s > 0; s >>= 1) {
            if (tid < s) red[tid] += red[tid + s];
            __syncthreads();
        }
        if (tid == 0) out[b * NC + c] = red[0] + bo[c];
        __syncthreads();
    }
}

// ---------------------------------------------------------------------------
extern "C" void kernel_launch(void* const* d_in, const int* in_sizes, int n_in,
                              void* d_out, int out_size) {
    const int*   sent   = (const int*)  d_in[0];
    const float* emb    = (const float*)d_in[1];
    const float* W_enc  = (const float*)d_in[2];
    const float* b_enc  = (const float*)d_in[3];
    const float* W_comp = (const float*)d_in[4];
    const float* b_comp = (const float*)d_in[5];
    const float* W_sel  = (const float*)d_in[6];
    // d_in[7] = b_sel (constant shift, softmax-invariant — not needed)
    const float* W1     = (const float*)d_in[8];
    const float* b1     = (const float*)d_in[9];
    const float* W2     = (const float*)d_in[10];
    const float* b2     = (const float*)d_in[11];
    const float* Wo     = (const float*)d_in[12];
    const float* bo     = (const float*)d_in[13];
    float* out = (float*)d_out;

    encode_kernel<<<NB * SEQ / 16, 256>>>(sent, emb, W_enc, b_enc);

    int cur = 0;
    for (int P = SEQ - 1; P >= 1; --P) {
        if (P >= 16) {
            dim3 grid(NB * P / 32, 2);   // BM=32 (TM=4)
            gates_gemm<4><<<grid, 256>>>(W_comp, b_comp, W_sel, P, cur);
        } else {
            dim3 grid(NB * P / 16, 2);   // BM=16 (TM=2) -> more blocks for small P
            gates_gemm<2><<<grid, 256>>>(W_comp, b_comp, W_sel, P, cur);
        }
        update_kernel<<<NB * 4, 256>>>(P, cur);
        cur ^= 1;
    }

    mlp_kernel<<<NB, 256>>>(W1, b1, W2, b2, Wo, bo, out, 1);  // 63 layers -> parity 1
}

// round 6
// speedup vs baseline: 1.8594x; 1.4377x over previous
#include <cuda_runtime.h>
#include <math.h>

#define NB 64          // batch
#define SEQ 64         // seq len
#define MD 256         // model dim
#define HF 128         // half
#define WD 300         // word dim
#define MLPD 1024
#define NC 3
#define BKT 16         // K tile
#define NKT (MD / BKT) // 16 k-tiles
#define XP 36          // Xs row stride in floats (pad: conflict-lite, 16B-aligned reads)

// Scratch (device globals — no runtime allocation allowed)
__device__ float g_states[2][NB * SEQ * MD];     // ping-pong state buffers
__device__ float g_comp[NB * (SEQ - 1) * MD];    // TreeLSTM [h,c] outputs
__device__ float g_lgpart[NB * (SEQ - 1) * 2];   // selection-logit partials (2 j-chunks)

__device__ __forceinline__ float sig_f(float x) { return 1.0f / (1.0f + __expf(-x)); }
__device__ __forceinline__ float tanh_f(float x) { return 1.0f - 2.0f / (__expf(2.0f * x) + 1.0f); }

// Packed f32x2 helpers (sm_100a; ptxas never auto-fuses these)
__device__ __forceinline__ unsigned long long pack2(float lo, float hi) {
    unsigned long long p;
    asm("mov.b64 %0, {%1, %2};" : "=l"(p) : "f"(lo), "f"(hi));
    return p;
}
__device__ __forceinline__ void unpack2(unsigned long long p, float& lo, float& hi) {
    asm("mov.b64 {%0, %1}, %2;" : "=f"(lo), "=f"(hi) : "l"(p));
}
__device__ __forceinline__ void fma2(unsigned long long& d, unsigned long long a, unsigned long long b) {
    asm("fma.rn.f32x2 %0, %1, %2, %0;" : "+l"(d) : "l"(a), "l"(b));
}
__device__ __forceinline__ void cp_async16(void* smem_dst, const void* gmem_src) {
    unsigned sa = (unsigned)__cvta_generic_to_shared(smem_dst);
    asm volatile("cp.async.cg.shared.global [%0], [%1], 16;" :: "r"(sa), "l"(gmem_src));
}
__device__ __forceinline__ void cp_commit() { asm volatile("cp.async.commit_group;"); }
__device__ __forceinline__ void cp_wait0()  { asm volatile("cp.async.wait_group 0;" ::: "memory"); }

// ---------------------------------------------------------------------------
// Encoder: states0[b][t][:] = embed[sent[b][t]] @ W_enc + b_enc
// ---------------------------------------------------------------------------
__global__ void encode_kernel(const int* __restrict__ sent,
                              const float* __restrict__ emb,
                              const float* __restrict__ W,
                              const float* __restrict__ bias) {
    __shared__ float se[16][WD];
    const int tok0 = blockIdx.x * 16;
    const int tid = threadIdx.x;
    for (int i = tid; i < 16 * WD; i += 256) {
        int t = i / WD, k = i - t * WD;
        se[t][k] = emb[(size_t)sent[tok0 + t] * WD + k];
    }
    __syncthreads();
    const int n = tid;
    float acc[16];
    float bv = bias[n];
#pragma unroll
    for (int t = 0; t < 16; t++) acc[t] = bv;
    for (int k = 0; k < WD; k++) {
        float w = W[k * MD + n];
#pragma unroll
        for (int t = 0; t < 16; t++) acc[t] += se[t][k] * w;
    }
    float* out = g_states[0];
#pragma unroll
    for (int t = 0; t < 16; t++) out[(size_t)(tok0 + t) * MD + n] = acc[t];
}

// ---------------------------------------------------------------------------
// Fused GEMM + TreeLSTM cell + logit partial.
// 128 threads (4 warps). Tile: BM = TM*4 rows x 64 gate-cols (jc) x 5 gates.
// Lane tx owns packed col pair {j0+2tx, j0+2tx+1}; warp ty owns TM rows.
// Inner loop per k: 5*TM FFMA2, 5 LDS.64 (W), uniform X LDS (broadcast).
// W tile streamed via double-buffered cp.async; X staged through registers.
// ---------------------------------------------------------------------------
template <int TM>
__global__ __launch_bounds__(128)
void gates_gemm(const float* __restrict__ Wc, const float* __restrict__ bc,
                const float* __restrict__ Wsel, int P, int in) {
    constexpr int BM = TM * 4;
    __shared__ float Xs[2][BKT][XP];
    __shared__ float Ws[2][BKT * 320];     // [k][g*64 + j]

    const float* __restrict__ S = g_states[in];
    const int tid = threadIdx.x;
    const int tx = tid & 31, ty = tid >> 5;
    const int jc = blockIdx.y;             // 0 or 1
    const int j0 = jc * 64;
    const int m0 = blockIdx.x * BM;

    // X loader: thread owns row mA, quad kqA (BM*4 float4 per tile)
    const int mA = tid >> 2;
    const int kqA = tid & 3;
    const bool hasA = (mA < BM);
    int roffA = 0;
    if (hasA) {
        int r = m0 + mA;
        int b = r / P;
        roffA = b * (SEQ * MD) + (r - b * P) * MD;
    }

    unsigned long long acc[TM][5];
#pragma unroll
    for (int i = 0; i < TM; i++)
#pragma unroll
        for (int g = 0; g < 5; g++) acc[i][g] = 0ull;

    float4 xr;

    // W prefetch: BKT*80 float4, 10 per thread. chunk=(k*5+g), dst offset chunk*64.
    auto prefW = [&](int kt, int buf) {
        const float* base = Wc + (size_t)kt * 640 + j0;
#pragma unroll
        for (int it = 0; it < 10; it++) {
            int I = it * 128 + tid;
            int chunk = I >> 4;            // 0..79
            int j4 = I & 15;
            int k = chunk / 5;
            int g = chunk - k * 5;
            cp_async16(&Ws[buf][chunk * 64 + j4 * 4],
                       base + (size_t)k * 640 + g * 128 + j4 * 4);
        }
    };
    auto ldX = [&](int kt) {
        if (hasA) {
            int xoff = kt + ((kt >= HF) ? HF : 0);
            xr = *reinterpret_cast<const float4*>(S + roffA + xoff + kqA * 4);
        }
    };
    auto stX = [&](int buf) {
        if (hasA) {
            float* xp = &Xs[buf][kqA * 4][mA];
            xp[0 * XP] = xr.x; xp[1 * XP] = xr.y;
            xp[2 * XP] = xr.z; xp[3 * XP] = xr.w;
        }
    };

    // Prologue: tile 0
    prefW(0, 0);
    cp_commit();
    ldX(0);
    stX(0);
    cp_wait0();
    __syncthreads();

    int buf = 0;
    for (int u = 0; u < NKT; u++, buf ^= 1) {
        if (u + 1 < NKT) {
            prefW((u + 1) * BKT, buf ^ 1);
            cp_commit();
            ldX((u + 1) * BKT);
        }
#pragma unroll 8
        for (int k = 0; k < BKT; k++) {
            const float* wp = &Ws[buf][k * 320] + 2 * tx;
            unsigned long long w0 = *reinterpret_cast<const unsigned long long*>(wp);
            unsigned long long w1 = *reinterpret_cast<const unsigned long long*>(wp + 64);
            unsigned long long w2 = *reinterpret_cast<const unsigned long long*>(wp + 128);
            unsigned long long w3 = *reinterpret_cast<const unsigned long long*>(wp + 192);
            unsigned long long w4 = *reinterpret_cast<const unsigned long long*>(wp + 256);
            const float* xp = &Xs[buf][k][ty * TM];
#pragma unroll
            for (int i = 0; i < TM; i += 4) {
                if constexpr (TM >= 4) {
                    float4 v = *reinterpret_cast<const float4*>(xp + i);
                    unsigned long long a0 = pack2(v.x, v.x);
                    unsigned long long a1 = pack2(v.y, v.y);
                    unsigned long long a2 = pack2(v.z, v.z);
                    unsigned long long a3 = pack2(v.w, v.w);
                    fma2(acc[i + 0][0], a0, w0); fma2(acc[i + 0][1], a0, w1);
                    fma2(acc[i + 0][2], a0, w2); fma2(acc[i + 0][3], a0, w3);
                    fma2(acc[i + 0][4], a0, w4);
                    fma2(acc[i + 1][0], a1, w0); fma2(acc[i + 1][1], a1, w1);
                    fma2(acc[i + 1][2], a1, w2); fma2(acc[i + 1][3], a1, w3);
                    fma2(acc[i + 1][4], a1, w4);
                    fma2(acc[i + 2][0], a2, w0); fma2(acc[i + 2][1], a2, w1);
                    fma2(acc[i + 2][2], a2, w2); fma2(acc[i + 2][3], a2, w3);
                    fma2(acc[i + 2][4], a2, w4);
                    fma2(acc[i + 3][0], a3, w0); fma2(acc[i + 3][1], a3, w1);
                    fma2(acc[i + 3][2], a3, w2); fma2(acc[i + 3][3], a3, w3);
                    fma2(acc[i + 3][4], a3, w4);
                } else {
                    float2 v = *reinterpret_cast<const float2*>(xp + i);
                    unsigned long long a0 = pack2(v.x, v.x);
                    unsigned long long a1 = pack2(v.y, v.y);
                    fma2(acc[i + 0][0], a0, w0); fma2(acc[i + 0][1], a0, w1);
                    fma2(acc[i + 0][2], a0, w2); fma2(acc[i + 0][3], a0, w3);
                    fma2(acc[i + 0][4], a0, w4);
                    fma2(acc[i + 1][0], a1, w0); fma2(acc[i + 1][1], a1, w1);
                    fma2(acc[i + 1][2], a1, w2); fma2(acc[i + 1][3], a1, w3);
                    fma2(acc[i + 1][4], a1, w4);
                }
            }
        }
        if (u + 1 < NKT) stX(buf ^ 1);
        cp_wait0();
        __syncthreads();
    }

    // Epilogue: bias + TreeLSTM cell + comp write + logit partial (2 cols/lane)
    const int j = j0 + 2 * tx;
    float2 wsh = *reinterpret_cast<const float2*>(Wsel + j);
    float2 wsc = *reinterpret_cast<const float2*>(Wsel + HF + j);
    float2 bb0 = *reinterpret_cast<const float2*>(bc + j);
    float2 bb1 = *reinterpret_cast<const float2*>(bc + 128 + j);
    float2 bb2 = *reinterpret_cast<const float2*>(bc + 256 + j);
    float2 bb3 = *reinterpret_cast<const float2*>(bc + 384 + j);
    float2 bb4 = *reinterpret_cast<const float2*>(bc + 512 + j);
#pragma unroll
    for (int i = 0; i < TM; i++) {
        int r = m0 + ty * TM + i;
        int b = r / P;
        int roff = b * (SEQ * MD) + (r - b * P) * MD;
        float2 cl = *reinterpret_cast<const float2*>(S + roff + HF + j);
        float2 cr = *reinterpret_cast<const float2*>(S + roff + MD + HF + j);
        float a0, a1, i0, i1, f10, f11, f20, f21, o0, o1;
        unpack2(acc[i][0], a0, a1);
        unpack2(acc[i][1], i0, i1);
        unpack2(acc[i][2], f10, f11);
        unpack2(acc[i][3], f20, f21);
        unpack2(acc[i][4], o0, o1);
        float c0 = tanh_f(a0 + bb0.x) * sig_f(i0 + bb1.x)
                 + sig_f(f10 + bb2.x) * cl.x + sig_f(f20 + bb3.x) * cr.x;
        float c1 = tanh_f(a1 + bb0.y) * sig_f(i1 + bb1.y)
                 + sig_f(f11 + bb2.y) * cl.y + sig_f(f21 + bb3.y) * cr.y;
        float h0 = sig_f(o0 + bb4.x) * tanh_f(c0);
        float h1 = sig_f(o1 + bb4.y) * tanh_f(c1);
        float* cp = g_comp + (size_t)r * MD;
        *reinterpret_cast<float2*>(cp + j) = make_float2(h0, h1);
        *reinterpret_cast<float2*>(cp + HF + j) = make_float2(c0, c1);
        float part = h0 * wsh.x + h1 * wsh.y + c0 * wsc.x + c1 * wsc.y;
#pragma unroll
        for (int o = 16; o > 0; o >>= 1) part += __shfl_xor_sync(0xFFFFFFFFu, part, o);
        if (tx == 0) g_lgpart[r * 2 + jc] = part;
    }
}

// ---------------------------------------------------------------------------
// Per-layer softmax + soft state update. 4 blocks per batch row.
// ---------------------------------------------------------------------------
__global__ __launch_bounds__(256)
void update_kernel(int P, int in) {
    __shared__ float lg[64], es[64], csn[64];
    __shared__ float prw[64], clw[64], crw[64];
    __shared__ float s_max, s_inv, s_tot;
    const int b = blockIdx.x >> 2, q = blockIdx.x & 3;
    const int tid = threadIdx.x;

    if (tid < 64) {
        float l = -3.0e38f;
        if (tid < P) {
            float2 v = *reinterpret_cast<const float2*>(g_lgpart + (((size_t)b * P + tid) << 1));
            l = v.x + v.y;
        }
        lg[tid] = l;
    }
    __syncthreads();
    if (tid < 32) {
        float v = fmaxf(lg[tid], lg[tid + 32]);
        for (int o = 16; o > 0; o >>= 1) v = fmaxf(v, __shfl_xor_sync(0xFFFFFFFFu, v, o));
        if (tid == 0) s_max = v;
    }
    __syncthreads();
    if (tid < 64) {
        float e = (tid < P) ? __expf(lg[tid] - s_max) : 0.f;
        es[tid] = e; csn[tid] = e;
    }
    __syncthreads();
    for (int off = 1; off < 64; off <<= 1) {
        float v = 0.f;
        if (tid < 64) { v = csn[tid]; if (tid >= off) v += csn[tid - off]; }
        __syncthreads();
        if (tid < 64) csn[tid] = v;
        __syncthreads();
    }
    if (tid == 0) { s_tot = csn[P - 1]; s_inv = 1.f / csn[P - 1]; }
    __syncthreads();
    if (tid < 64) {
        float inv = s_inv, e = es[tid], cv = csn[tid];
        prw[tid] = e * inv;
        crw[tid] = (cv - e) * inv;
        clw[tid] = (s_tot - cv) * inv;
    }
    __syncthreads();
    const float* Sb = g_states[in] + b * SEQ * MD;
    float* Ob = g_states[in ^ 1] + b * SEQ * MD;
    const float* Cb = g_comp + (size_t)b * P * MD;
    for (int p = q; p < P; p += 4) {
        Ob[p * MD + tid] = clw[p] * Sb[p * MD + tid]
                         + crw[p] * Sb[(p + 1) * MD + tid]
                         + prw[p] * Cb[p * MD + tid];
    }
}

// ---------------------------------------------------------------------------
// Final MLP: relu(relu(h@W1+b1)@W2+b2)@W_out + b_out. One block per row.
// ---------------------------------------------------------------------------
__global__ void mlp_kernel(const float* __restrict__ W1, const float* __restrict__ b1,
                           const float* __restrict__ W2, const float* __restrict__ b2,
                           const float* __restrict__ Wo, const float* __restrict__ bo,
                           float* __restrict__ out, int in) {
    const int b = blockIdx.x, tid = threadIdx.x;
    __shared__ float h0[MD];
    __shared__ float h1[MLPD];
    __shared__ float h2[MLPD];
    __shared__ float red[256];
    const float* S = g_states[in] + (size_t)b * SEQ * MD;
    for (int i = tid; i < MD; i += 256) h0[i] = S[i];
    __syncthreads();
#pragma unroll
    for (int ni = 0; ni < MLPD / 256; ni++) {
        int n = tid + ni * 256;
        float acc = b1[n];
        for (int k = 0; k < MD; k++) acc += h0[k] * W1[(size_t)k * MLPD + n];
        h1[n] = fmaxf(acc, 0.f);
    }
    __syncthreads();
#pragma unroll
    for (int ni = 0; ni < MLPD / 256; ni++) {
        int n = tid + ni * 256;
        float acc = b2[n];
        for (int k = 0; k < MLPD; k++) acc += h1[k] * W2[(size_t)k * MLPD + n];
        h2[n] = fmaxf(acc, 0.f);
    }
    __syncthreads();
    for (int c = 0; c < NC; c++) {
        float part = 0.f;
        for (int k = tid; k < MLPD; k += 256) part += h2[k] * Wo[(size_t)k * NC + c];
        red[tid] = part;
        __syncthreads();
        for (int s = 128; s > 0; s >>= 1) {
            if (tid < s) red[tid] += red[tid + s];
            __syncthreads();
        }
        if (tid == 0) out[b * NC + c] = red[0] + bo[c];
        __syncthreads();
    }
}

// ---------------------------------------------------------------------------
extern "C" void kernel_launch(void* const* d_in, const int* in_sizes, int n_in,
                              void* d_out, int out_size) {
    const int*   sent   = (const int*)  d_in[0];
    const float* emb    = (const float*)d_in[1];
    const float* W_enc  = (const float*)d_in[2];
    const float* b_enc  = (const float*)d_in[3];
    const float* W_comp = (const float*)d_in[4];
    const float* b_comp = (const float*)d_in[5];
    const float* W_sel  = (const float*)d_in[6];
    // d_in[7] = b_sel (constant shift, softmax-invariant — not needed)
    const float* W1     = (const float*)d_in[8];
    const float* b1     = (const float*)d_in[9];
    const float* W2     = (const float*)d_in[10];
    const float* b2     = (const float*)d_in[11];
    const float* Wo     = (const float*)d_in[12];
    const float* bo     = (const float*)d_in[13];
    float* out = (float*)d_out;

    encode_kernel<<<NB * SEQ / 16, 256>>>(sent, emb, W_enc, b_enc);

    int cur = 0;
    for (int P = SEQ - 1; P >= 1; --P) {
        if (P >= 30) {
            dim3 grid(NB * P / 32, 2);   // BM=32 (TM=8)
            gates_gemm<8><<<grid, 128>>>(W_comp, b_comp, W_sel, P, cur);
        } else if (P >= 8) {
            dim3 grid(NB * P / 16, 2);   // BM=16 (TM=4)
            gates_gemm<4><<<grid, 128>>>(W_comp, b_comp, W_sel, P, cur);
        } else {
            dim3 grid(NB * P / 8, 2);    // BM=8 (TM=2)
            gates_gemm<2><<<grid, 128>>>(W_comp, b_comp, W_sel, P, cur);
        }
        update_kernel<<<NB * 4, 256>>>(P, cur);
        cur ^= 1;
    }

    mlp_kernel<<<NB, 256>>>(W1, b1, W2, b2, Wo, bo, out, 1);  // 63 layers -> parity 1
}

// round 8
// speedup vs baseline: 1.9200x; 1.0326x over previous
#include <cuda_runtime.h>
#include <math.h>

#define NB 64          // batch
#define SEQ 64         // seq len
#define MD 256         // model dim
#define HF 128         // half
#define WD 300         // word dim
#define MLPD 1024
#define NC 3
#define BKT 8          // K tile (halved vs R6: smem/2 -> 2 blocks/SM)
#define NKT (MD / BKT) // 32 k-tiles
#define XP 36          // Xs row stride in floats (pad; 16B-aligned)

// Scratch (device globals — no runtime allocation allowed)
__device__ float g_states[2][NB * SEQ * MD];     // ping-pong state buffers
__device__ float g_comp[NB * (SEQ - 1) * MD];    // TreeLSTM [h,c] outputs
__device__ float g_lgpart[NB * (SEQ - 1) * 2];   // selection-logit partials (2 j-chunks)

__device__ __forceinline__ float sig_f(float x) { return 1.0f / (1.0f + __expf(-x)); }
__device__ __forceinline__ float tanh_f(float x) { return 1.0f - 2.0f / (__expf(2.0f * x) + 1.0f); }

// Packed f32x2 helpers (sm_100a; ptxas never auto-fuses these)
__device__ __forceinline__ unsigned long long pack2(float lo, float hi) {
    unsigned long long p;
    asm("mov.b64 %0, {%1, %2};" : "=l"(p) : "f"(lo), "f"(hi));
    return p;
}
__device__ __forceinline__ void unpack2(unsigned long long p, float& lo, float& hi) {
    asm("mov.b64 {%0, %1}, %2;" : "=f"(lo), "=f"(hi) : "l"(p));
}
__device__ __forceinline__ void fma2(unsigned long long& d, unsigned long long a, unsigned long long b) {
    asm("fma.rn.f32x2 %0, %1, %2, %0;" : "+l"(d) : "l"(a), "l"(b));
}
__device__ __forceinline__ void cp_async16(void* smem_dst, const void* gmem_src) {
    unsigned sa = (unsigned)__cvta_generic_to_shared(smem_dst);
    asm volatile("cp.async.cg.shared.global [%0], [%1], 16;" :: "r"(sa), "l"(gmem_src));
}
__device__ __forceinline__ void cp_commit() { asm volatile("cp.async.commit_group;"); }
__device__ __forceinline__ void cp_wait0()  { asm volatile("cp.async.wait_group 0;" ::: "memory"); }

// ---------------------------------------------------------------------------
// Encoder: states0[b][t][:] = embed[sent[b][t]] @ W_enc + b_enc
// ---------------------------------------------------------------------------
__global__ void encode_kernel(const int* __restrict__ sent,
                              const float* __restrict__ emb,
                              const float* __restrict__ W,
                              const float* __restrict__ bias) {
    __shared__ float se[16][WD];
    const int tok0 = blockIdx.x * 16;
    const int tid = threadIdx.x;
    for (int i = tid; i < 16 * WD; i += 256) {
        int t = i / WD, k = i - t * WD;
        se[t][k] = emb[(size_t)sent[tok0 + t] * WD + k];
    }
    __syncthreads();
    const int n = tid;
    float acc[16];
    float bv = bias[n];
#pragma unroll
    for (int t = 0; t < 16; t++) acc[t] = bv;
    for (int k = 0; k < WD; k++) {
        float w = W[k * MD + n];
#pragma unroll
        for (int t = 0; t < 16; t++) acc[t] += se[t][k] * w;
    }
    float* out = g_states[0];
#pragma unroll
    for (int t = 0; t < 16; t++) out[(size_t)(tok0 + t) * MD + n] = acc[t];
}

// ---------------------------------------------------------------------------
// Fused GEMM + TreeLSTM cell + logit partial.
// 128 threads (4 warps), 2 blocks/SM (smem ~22.5 KB). Tile: BM = TM*4 rows x
// 64 gate-cols (jc) x 5 gates. Lane tx owns packed col pair {j0+2tx, j0+2tx+1};
// warp ty owns TM rows. Inner loop per k: 5*TM FFMA2, 5 LDS.64 (W), uniform
// X LDS (broadcast). Double-buffered cp.async for W; X staged via registers.
// ---------------------------------------------------------------------------
template <int TM>
__global__ __launch_bounds__(128, 2)
void gates_gemm(const float* __restrict__ Wc, const float* __restrict__ bc,
                const float* __restrict__ Wsel, int P, int in) {
    constexpr int BM = TM * 4;
    __shared__ float Xs[2][BKT][XP];
    __shared__ float Ws[2][BKT * 320];     // [k][g*64 + j]

    const float* __restrict__ S = g_states[in];
    const int tid = threadIdx.x;
    const int tx = tid & 31, ty = tid >> 5;
    const int jc = blockIdx.y;             // 0 or 1
    const int j0 = jc * 64;
    const int m0 = blockIdx.x * BM;

    // X loader: BM rows x 2 quads (BKT=8 -> 2 float4 per row)
    const int mA = tid >> 1;
    const int kqA = tid & 1;
    const bool hasA = (mA < BM);
    int roffA = 0;
    if (hasA) {
        int r = m0 + mA;
        int b = r / P;
        roffA = b * (SEQ * MD) + (r - b * P) * MD;
    }

    unsigned long long acc[TM][5];
#pragma unroll
    for (int i = 0; i < TM; i++)
#pragma unroll
        for (int g = 0; g < 5; g++) acc[i][g] = 0ull;

    float4 xr;

    // W prefetch: BKT*80 = 640 float4, 5 per thread. chunk=(k*5+g), 16 float4 each.
    auto prefW = [&](int kt, int buf) {
        const float* base = Wc + (size_t)kt * 640 + j0;
#pragma unroll
        for (int it = 0; it < 5; it++) {
            int I = it * 128 + tid;
            int chunk = I >> 4;            // 0..39
            int j4 = I & 15;
            int k = chunk / 5;
            int g = chunk - k * 5;
            cp_async16(&Ws[buf][chunk * 64 + j4 * 4],
                       base + (size_t)k * 640 + g * 128 + j4 * 4);
        }
    };
    auto ldX = [&](int kt) {
        if (hasA) {
            int xoff = kt + ((kt >= HF) ? HF : 0);
            xr = *reinterpret_cast<const float4*>(S + roffA + xoff + kqA * 4);
        }
    };
    auto stX = [&](int buf) {
        if (hasA) {
            float* xp = &Xs[buf][kqA * 4][mA];
            xp[0 * XP] = xr.x; xp[1 * XP] = xr.y;
            xp[2 * XP] = xr.z; xp[3 * XP] = xr.w;
        }
    };

    // Prologue: tile 0
    prefW(0, 0);
    cp_commit();
    ldX(0);
    stX(0);
    cp_wait0();
    __syncthreads();

    int buf = 0;
    for (int u = 0; u < NKT; u++, buf ^= 1) {
        if (u + 1 < NKT) {
            prefW((u + 1) * BKT, buf ^ 1);
            cp_commit();
            ldX((u + 1) * BKT);
        }
#pragma unroll
        for (int k = 0; k < BKT; k++) {
            const float* wp = &Ws[buf][k * 320] + 2 * tx;
            unsigned long long w0 = *reinterpret_cast<const unsigned long long*>(wp);
            unsigned long long w1 = *reinterpret_cast<const unsigned long long*>(wp + 64);
            unsigned long long w2 = *reinterpret_cast<const unsigned long long*>(wp + 128);
            unsigned long long w3 = *reinterpret_cast<const unsigned long long*>(wp + 192);
            unsigned long long w4 = *reinterpret_cast<const unsigned long long*>(wp + 256);
            const float* xp = &Xs[buf][k][ty * TM];
#pragma unroll
            for (int i = 0; i < TM; i += 4) {
                if constexpr (TM >= 4) {
                    float4 v = *reinterpret_cast<const float4*>(xp + i);
                    unsigned long long a0 = pack2(v.x, v.x);
                    unsigned long long a1 = pack2(v.y, v.y);
                    unsigned long long a2 = pack2(v.z, v.z);
                    unsigned long long a3 = pack2(v.w, v.w);
                    fma2(acc[i + 0][0], a0, w0); fma2(acc[i + 0][1], a0, w1);
                    fma2(acc[i + 0][2], a0, w2); fma2(acc[i + 0][3], a0, w3);
                    fma2(acc[i + 0][4], a0, w4);
                    fma2(acc[i + 1][0], a1, w0); fma2(acc[i + 1][1], a1, w1);
                    fma2(acc[i + 1][2], a1, w2); fma2(acc[i + 1][3], a1, w3);
                    fma2(acc[i + 1][4], a1, w4);
                    fma2(acc[i + 2][0], a2, w0); fma2(acc[i + 2][1], a2, w1);
                    fma2(acc[i + 2][2], a2, w2); fma2(acc[i + 2][3], a2, w3);
                    fma2(acc[i + 2][4], a2, w4);
                    fma2(acc[i + 3][0], a3, w0); fma2(acc[i + 3][1], a3, w1);
                    fma2(acc[i + 3][2], a3, w2); fma2(acc[i + 3][3], a3, w3);
                    fma2(acc[i + 3][4], a3, w4);
                } else {
                    float2 v = *reinterpret_cast<const float2*>(xp + i);
                    unsigned long long a0 = pack2(v.x, v.x);
                    unsigned long long a1 = pack2(v.y, v.y);
                    fma2(acc[i + 0][0], a0, w0); fma2(acc[i + 0][1], a0, w1);
                    fma2(acc[i + 0][2], a0, w2); fma2(acc[i + 0][3], a0, w3);
                    fma2(acc[i + 0][4], a0, w4);
                    fma2(acc[i + 1][0], a1, w0); fma2(acc[i + 1][1], a1, w1);
                    fma2(acc[i + 1][2], a1, w2); fma2(acc[i + 1][3], a1, w3);
                    fma2(acc[i + 1][4], a1, w4);
                }
            }
        }
        if (u + 1 < NKT) stX(buf ^ 1);
        cp_wait0();
        __syncthreads();
    }

    // Epilogue: bias + TreeLSTM cell + comp write + logit partial (2 cols/lane)
    const int j = j0 + 2 * tx;
    float2 wsh = *reinterpret_cast<const float2*>(Wsel + j);
    float2 wsc = *reinterpret_cast<const float2*>(Wsel + HF + j);
    float2 bb0 = *reinterpret_cast<const float2*>(bc + j);
    float2 bb1 = *reinterpret_cast<const float2*>(bc + 128 + j);
    float2 bb2 = *reinterpret_cast<const float2*>(bc + 256 + j);
    float2 bb3 = *reinterpret_cast<const float2*>(bc + 384 + j);
    float2 bb4 = *reinterpret_cast<const float2*>(bc + 512 + j);
#pragma unroll
    for (int i = 0; i < TM; i++) {
        int r = m0 + ty * TM + i;
        int b = r / P;
        int roff = b * (SEQ * MD) + (r - b * P) * MD;
        float2 cl = *reinterpret_cast<const float2*>(S + roff + HF + j);
        float2 cr = *reinterpret_cast<const float2*>(S + roff + MD + HF + j);
        float a0, a1, i0, i1, f10, f11, f20, f21, o0, o1;
        unpack2(acc[i][0], a0, a1);
        unpack2(acc[i][1], i0, i1);
        unpack2(acc[i][2], f10, f11);
        unpack2(acc[i][3], f20, f21);
        unpack2(acc[i][4], o0, o1);
        float c0 = tanh_f(a0 + bb0.x) * sig_f(i0 + bb1.x)
                 + sig_f(f10 + bb2.x) * cl.x + sig_f(f20 + bb3.x) * cr.x;
        float c1 = tanh_f(a1 + bb0.y) * sig_f(i1 + bb1.y)
                 + sig_f(f11 + bb2.y) * cl.y + sig_f(f21 + bb3.y) * cr.y;
        float h0 = sig_f(o0 + bb4.x) * tanh_f(c0);
        float h1 = sig_f(o1 + bb4.y) * tanh_f(c1);
        float* cp = g_comp + (size_t)r * MD;
        *reinterpret_cast<float2*>(cp + j) = make_float2(h0, h1);
        *reinterpret_cast<float2*>(cp + HF + j) = make_float2(c0, c1);
        float part = h0 * wsh.x + h1 * wsh.y + c0 * wsc.x + c1 * wsc.y;
#pragma unroll
        for (int o = 16; o > 0; o >>= 1) part += __shfl_xor_sync(0xFFFFFFFFu, part, o);
        if (tx == 0) g_lgpart[r * 2 + jc] = part;
    }
}

// ---------------------------------------------------------------------------
// Per-layer softmax + soft state update. 4 blocks per batch row.
// ---------------------------------------------------------------------------
__global__ __launch_bounds__(256)
void update_kernel(int P, int in) {
    __shared__ float lg[64], es[64], csn[64];
    __shared__ float prw[64], clw[64], crw[64];
    __shared__ float s_max, s_inv, s_tot;
    const int b = blockIdx.x >> 2, q = blockIdx.x & 3;
    const int tid = threadIdx.x;

    if (tid < 64) {
        float l = -3.0e38f;
        if (tid < P) {
            float2 v = *reinterpret_cast<const float2*>(g_lgpart + (((size_t)b * P + tid) << 1));
            l = v.x + v.y;
        }
        lg[tid] = l;
    }
    __syncthreads();
    if (tid < 32) {
        float v = fmaxf(lg[tid], lg[tid + 32]);
        for (int o = 16; o > 0; o >>= 1) v = fmaxf(v, __shfl_xor_sync(0xFFFFFFFFu, v, o));
        if (tid == 0) s_max = v;
    }
    __syncthreads();
    if (tid < 64) {
        float e = (tid < P) ? __expf(lg[tid] - s_max) : 0.f;
        es[tid] = e; csn[tid] = e;
    }
    __syncthreads();
    for (int off = 1; off < 64; off <<= 1) {
        float v = 0.f;
        if (tid < 64) { v = csn[tid]; if (tid >= off) v += csn[tid - off]; }
        __syncthreads();
        if (tid < 64) csn[tid] = v;
        __syncthreads();
    }
    if (tid == 0) { s_tot = csn[P - 1]; s_inv = 1.f / csn[P - 1]; }
    __syncthreads();
    if (tid < 64) {
        float inv = s_inv, e = es[tid], cv = csn[tid];
        prw[tid] = e * inv;
        crw[tid] = (cv - e) * inv;
        clw[tid] = (s_tot - cv) * inv;
    }
    __syncthreads();
    const float* Sb = g_states[in] + b * SEQ * MD;
    float* Ob = g_states[in ^ 1] + b * SEQ * MD;
    const float* Cb = g_comp + (size_t)b * P * MD;
    for (int p = q; p < P; p += 4) {
        Ob[p * MD + tid] = clw[p] * Sb[p * MD + tid]
                         + crw[p] * Sb[(p + 1) * MD + tid]
                         + prw[p] * Cb[p * MD + tid];
    }
}

// ---------------------------------------------------------------------------
// Final MLP: relu(relu(h@W1+b1)@W2+b2)@W_out + b_out. One block per row.
// ---------------------------------------------------------------------------
__global__ void mlp_kernel(const float* __restrict__ W1, const float* __restrict__ b1,
                           const float* __restrict__ W2, const float* __restrict__ b2,
                           const float* __restrict__ Wo, const float* __restrict__ bo,
                           float* __restrict__ out, int in) {
    const int b = blockIdx.x, tid = threadIdx.x;
    __shared__ float h0[MD];
    __shared__ float h1[MLPD];
    __shared__ float h2[MLPD];
    __shared__ float red[256];
    const float* S = g_states[in] + (size_t)b * SEQ * MD;
    for (int i = tid; i < MD; i += 256) h0[i] = S[i];
    __syncthreads();
#pragma unroll
    for (int ni = 0; ni < MLPD / 256; ni++) {
        int n = tid + ni * 256;
        float acc = b1[n];
        for (int k = 0; k < MD; k++) acc += h0[k] * W1[(size_t)k * MLPD + n];
        h1[n] = fmaxf(acc, 0.f);
    }
    __syncthreads();
#pragma unroll
    for (int ni = 0; ni < MLPD / 256; ni++) {
        int n = tid + ni * 256;
        float acc = b2[n];
        for (int k = 0; k < MLPD; k++) acc += h1[k] * W2[(size_t)k * MLPD + n];
        h2[n] = fmaxf(acc, 0.f);
    }
    __syncthreads();
    for (int c = 0; c < NC; c++) {
        float part = 0.f;
        for (int k = tid; k < MLPD; k += 256) part += h2[k] * Wo[(size_t)k * NC + c];
        red[tid] = part;
        __syncthreads();
        for (int s = 128; s > 0; s >>= 1) {
            if (tid < s) red[tid] += red[tid + s];
            __syncthreads();
        }
        if (tid == 0) out[b * NC + c] = red[0] + bo[c];
        __syncthreads();
    }
}

// ---------------------------------------------------------------------------
extern "C" void kernel_launch(void* const* d_in, const int* in_sizes, int n_in,
                              void* d_out, int out_size) {
    const int*   sent   = (const int*)  d_in[0];
    const float* emb    = (const float*)d_in[1];
    const float* W_enc  = (const float*)d_in[2];
    const float* b_enc  = (const float*)d_in[3];
    const float* W_comp = (const float*)d_in[4];
    const float* b_comp = (const float*)d_in[5];
    const float* W_sel  = (const float*)d_in[6];
    // d_in[7] = b_sel (constant shift, softmax-invariant — not needed)
    const float* W1     = (const float*)d_in[8];
    const float* b1     = (const float*)d_in[9];
    const float* W2     = (const float*)d_in[10];
    const float* b2     = (const float*)d_in[11];
    const float* Wo     = (const float*)d_in[12];
    const float* bo     = (const float*)d_in[13];
    float* out = (float*)d_out;

    encode_kernel<<<NB * SEQ / 16, 256>>>(sent, emb, W_enc, b_enc);

    int cur = 0;
    for (int P = SEQ - 1; P >= 1; --P) {
        if (P >= 30) {
            dim3 grid(NB * P / 32, 2);   // BM=32 (TM=8)
            gates_gemm<8><<<grid, 128>>>(W_comp, b_comp, W_sel, P, cur);
        } else if (P >= 8) {
            dim3 grid(NB * P / 16, 2);   // BM=16 (TM=4)
            gates_gemm<4><<<grid, 128>>>(W_comp, b_comp, W_sel, P, cur);
        } else {
            dim3 grid(NB * P / 8, 2);    // BM=8 (TM=2)
            gates_gemm<2><<<grid, 128>>>(W_comp, b_comp, W_sel, P, cur);
        }
        update_kernel<<<NB * 4, 256>>>(P, cur);
        cur ^= 1;
    }

    mlp_kernel<<<NB, 256>>>(W1, b1, W2, b2, Wo, bo, out, 1);  // 63 layers -> parity 1
}